// round 2
// baseline (speedup 1.0000x reference)
#include <cuda_runtime.h>

constexpr int NDRUG = 50000;
constexpr int NGENE = 50000;
constexpr int DHID  = 64;
constexpr int DEMB  = 32;

// Scratch (device globals — no allocation allowed)
__device__ float g_tm[4][NDRUG * DHID];   // transformed src features per relation
__device__ float g_acc[4][NDRUG * DHID];  // per-relation segment-sum accumulators
__device__ float g_h[2][NDRUG * DHID];    // hidden layer outputs (hd, hg)
__device__ float g_deg[4][NDRUG];         // per-relation in-degree of dst nodes

struct Ptr4  { const float* p[4]; };
struct Iptr4 { const int*   p[4]; };
struct Fptr4 { float*       p[4]; };

// ---------------------------------------------------------------------------
// degree histogram, all 4 relations in one launch (gridDim.y = relation)
// ---------------------------------------------------------------------------
__global__ void degree4_kernel(Iptr4 dst, float* __restrict__ deg, int E) {
    int r = blockIdx.y;
    int i = blockIdx.x * blockDim.x + threadIdx.x;
    if (i < E) atomicAdd(&deg[r * NDRUG + dst.p[r][i]], 1.0f);
}

// ---------------------------------------------------------------------------
// Tiled fp32 GEMM, 4 relations per launch: Y[r][M,N] = X[r][M,K] @ W[r][K,N]
// BM=128, full-N block, BK=32, 256 threads, thread tile TM=8 x TN=N/16
// ---------------------------------------------------------------------------
template<int K, int N>
__launch_bounds__(256)
__global__ void gemm4_kernel(Ptr4 Xa, Ptr4 Wa, Fptr4 Ya, int M) {
    constexpr int BM = 128, BK = 32;
    constexpr int TM = 8, TN = N / 16;
    const int r = blockIdx.y;
    const float* __restrict__ X = Xa.p[r];
    const float* __restrict__ W = Wa.p[r];
    float* __restrict__ Y = Ya.p[r];

    __shared__ float Xs[BM][BK + 4];
    __shared__ float Ws[BK][N + 4];
    const int tid  = threadIdx.x;
    const int trow = tid >> 4;      // 0..15
    const int tcol = tid & 15;      // 0..15
    const int m0   = blockIdx.x * BM;

    float acc[TM][TN];
#pragma unroll
    for (int i = 0; i < TM; i++)
#pragma unroll
        for (int j = 0; j < TN; j++) acc[i][j] = 0.f;

    for (int k0 = 0; k0 < K; k0 += BK) {
        // load X tile (128 x 32 floats) via float4, 4 per thread
#pragma unroll
        for (int i = 0; i < 4; i++) {
            int lin = tid + i * 256;        // float4 index, 0..1023
            int row = lin >> 3;             // 8 float4 per row
            int c4  = (lin & 7) * 4;
            int gr  = m0 + row;
            float4 v = make_float4(0.f, 0.f, 0.f, 0.f);
            if (gr < M) v = *(const float4*)(X + (size_t)gr * K + k0 + c4);
            Xs[row][c4 + 0] = v.x; Xs[row][c4 + 1] = v.y;
            Xs[row][c4 + 2] = v.z; Xs[row][c4 + 3] = v.w;
        }
        // load W tile (32 x N floats)
        constexpr int WF4 = BK * N / 4;
#pragma unroll
        for (int i = 0; i < (WF4 + 255) / 256; i++) {
            int lin = tid + i * 256;
            if (lin < WF4) {
                int row = lin / (N / 4);
                int c4  = (lin % (N / 4)) * 4;
                float4 v = *(const float4*)(W + (size_t)(k0 + row) * N + c4);
                Ws[row][c4 + 0] = v.x; Ws[row][c4 + 1] = v.y;
                Ws[row][c4 + 2] = v.z; Ws[row][c4 + 3] = v.w;
            }
        }
        __syncthreads();
#pragma unroll
        for (int k = 0; k < BK; k++) {
            float a[TM], b[TN];
#pragma unroll
            for (int i = 0; i < TM; i++) a[i] = Xs[trow * TM + i][k];
#pragma unroll
            for (int j = 0; j < TN; j++) b[j] = Ws[k][tcol * TN + j];
#pragma unroll
            for (int i = 0; i < TM; i++)
#pragma unroll
                for (int j = 0; j < TN; j++) acc[i][j] += a[i] * b[j];
        }
        __syncthreads();
    }
#pragma unroll
    for (int i = 0; i < TM; i++) {
        int gr = m0 + trow * TM + i;
        if (gr < M) {
#pragma unroll
            for (int j = 0; j < TN; j++)
                Y[(size_t)gr * N + tcol * TN + j] = acc[i][j];
        }
    }
}

// ---------------------------------------------------------------------------
// Edge scatter, 4 relations per launch: acc[r][dst] += m[r][src]
// One float4 per thread, single vector atomic (RED.128) — sm_90+ intrinsic.
// ---------------------------------------------------------------------------
template<int D>
__global__ void scatter4_kernel(Ptr4 ma, Iptr4 srca, Iptr4 dsta, Fptr4 acca, int E) {
    constexpr int C = D / 4;
    const int r = blockIdx.y;
    int idx = blockIdx.x * blockDim.x + threadIdx.x;
    if (idx >= E * C) return;
    int e = idx / C;
    int c = idx % C;
    int s = srca.p[r][e];
    int d = dsta.p[r][e];
    float4 v = *(const float4*)(ma.p[r] + (size_t)s * D + c * 4);
    float4* o = (float4*)(acca.p[r] + (size_t)d * D + c * 4);
    atomicAdd(o, v);   // vector atomic add (f32x4), sm_90+
}

// ---------------------------------------------------------------------------
// Combine: out = accA/max(degA,1) + accB/max(degB,1) + bias  (optional relu)
// ---------------------------------------------------------------------------
template<int D, bool RELU>
__global__ void combine_kernel(const float* __restrict__ accA, const float* __restrict__ degA,
                               const float* __restrict__ accB, const float* __restrict__ degB,
                               const float* __restrict__ bias, float* __restrict__ out, int n) {
    constexpr int C = D / 4;
    int idx = blockIdx.x * blockDim.x + threadIdx.x;
    if (idx >= n * C) return;
    int node = idx / C;
    int c    = idx % C;
    float ia = 1.0f / fmaxf(degA[node], 1.0f);
    float ib = 1.0f / fmaxf(degB[node], 1.0f);
    float4 a  = ((const float4*)accA)[idx];
    float4 b  = ((const float4*)accB)[idx];
    float4 bs = *(const float4*)(bias + c * 4);
    float4 rr;
    rr.x = a.x * ia + b.x * ib + bs.x;
    rr.y = a.y * ia + b.y * ib + bs.y;
    rr.z = a.z * ia + b.z * ib + bs.z;
    rr.w = a.w * ia + b.w * ib + bs.w;
    if (RELU) {
        rr.x = fmaxf(rr.x, 0.f); rr.y = fmaxf(rr.y, 0.f);
        rr.z = fmaxf(rr.z, 0.f); rr.w = fmaxf(rr.w, 0.f);
    }
    ((float4*)out)[idx] = rr;
}

// ---------------------------------------------------------------------------
// Orchestration
// Relations: 0=dd (drug->drug), 1=dg (drug->gene), 2=gd (gene->drug), 3=gg
//   hd = mean_dd + mean_gd + b_drug ; hg = mean_dg + mean_gg + b_gene
// ---------------------------------------------------------------------------
extern "C" void kernel_launch(void* const* d_in, const int* in_sizes, int n_in,
                              void* d_out, int out_size) {
    const float* xd = (const float*)d_in[0];
    const float* xg = (const float*)d_in[1];
    const int* es[8];
    for (int i = 0; i < 8; i++) es[i] = (const int*)d_in[2 + i];
    // es: 0=dd_src 1=dd_dst 2=dg_src 3=dg_dst 4=gd_src 5=gd_dst 6=gg_src 7=gg_dst
    const float* W1[4] = {(const float*)d_in[10], (const float*)d_in[11],
                          (const float*)d_in[12], (const float*)d_in[13]};
    const float* b1d = (const float*)d_in[14];
    const float* b1g = (const float*)d_in[15];
    const float* W2[4] = {(const float*)d_in[16], (const float*)d_in[17],
                          (const float*)d_in[18], (const float*)d_in[19]};
    const float* b2d = (const float*)d_in[20];
    const float* b2g = (const float*)d_in[21];
    float* out = (float*)d_out;
    const int E = in_sizes[2];

    float *tm, *acc, *h, *deg;
    cudaGetSymbolAddress((void**)&tm,  g_tm);
    cudaGetSymbolAddress((void**)&acc, g_acc);
    cudaGetSymbolAddress((void**)&h,   g_h);
    cudaGetSymbolAddress((void**)&deg, g_deg);

    const int TB = 256;
    const int gblk = (NDRUG + 127) / 128;

    Iptr4 srcs = {{es[0], es[2], es[4], es[6]}};
    Iptr4 dsts = {{es[1], es[3], es[5], es[7]}};

    // --- degrees (shared by both layers), one fused launch ---
    cudaMemsetAsync(deg, 0, sizeof(float) * 4 * NDRUG, 0);
    degree4_kernel<<<dim3((E + TB - 1) / TB, 4), TB>>>(dsts, deg, E);

    // --- layer 1: D_IN=128 -> D_HID=64, relu ---
    cudaMemsetAsync(acc, 0, sizeof(float) * 4 * NDRUG * DHID, 0);
    {
        Ptr4  X1 = {{xd, xd, xg, xg}};
        Ptr4  Wp = {{W1[0], W1[1], W1[2], W1[3]}};
        Fptr4 Yp = {{tm + 0 * (size_t)NDRUG * DHID, tm + 1 * (size_t)NDRUG * DHID,
                     tm + 2 * (size_t)NDRUG * DHID, tm + 3 * (size_t)NDRUG * DHID}};
        gemm4_kernel<128, 64><<<dim3(gblk, 4), 256>>>(X1, Wp, Yp, NDRUG);

        Ptr4  Mp = {{Yp.p[0], Yp.p[1], Yp.p[2], Yp.p[3]}};
        Fptr4 Ap = {{acc + 0 * (size_t)NDRUG * DHID, acc + 1 * (size_t)NDRUG * DHID,
                     acc + 2 * (size_t)NDRUG * DHID, acc + 3 * (size_t)NDRUG * DHID}};
        int n = E * (DHID / 4);
        scatter4_kernel<64><<<dim3((n + TB - 1) / TB, 4), TB>>>(Mp, srcs, dsts, Ap, E);

        int nc = NDRUG * (DHID / 4);
        combine_kernel<64, true><<<(nc + TB - 1) / TB, TB>>>(
            Ap.p[0], deg + 0 * NDRUG, Ap.p[2], deg + 2 * NDRUG, b1d, h, NDRUG);
        combine_kernel<64, true><<<(nc + TB - 1) / TB, TB>>>(
            Ap.p[1], deg + 1 * NDRUG, Ap.p[3], deg + 3 * NDRUG, b1g,
            h + (size_t)NDRUG * DHID, NGENE);
    }

    // --- layer 2: D_HID=64 -> D_EMB=32, no relu ---
    cudaMemsetAsync(acc, 0, sizeof(float) * 4 * NDRUG * DEMB, 0);
    {
        const float* hd = h;
        const float* hg = h + (size_t)NDRUG * DHID;
        Ptr4  X2 = {{hd, hd, hg, hg}};
        Ptr4  Wp = {{W2[0], W2[1], W2[2], W2[3]}};
        Fptr4 Yp = {{tm + 0 * (size_t)NDRUG * DEMB, tm + 1 * (size_t)NDRUG * DEMB,
                     tm + 2 * (size_t)NDRUG * DEMB, tm + 3 * (size_t)NDRUG * DEMB}};
        gemm4_kernel<64, 32><<<dim3(gblk, 4), 256>>>(X2, Wp, Yp, NDRUG);

        Ptr4  Mp = {{Yp.p[0], Yp.p[1], Yp.p[2], Yp.p[3]}};
        Fptr4 Ap = {{acc + 0 * (size_t)NDRUG * DEMB, acc + 1 * (size_t)NDRUG * DEMB,
                     acc + 2 * (size_t)NDRUG * DEMB, acc + 3 * (size_t)NDRUG * DEMB}};
        int n = E * (DEMB / 4);
        scatter4_kernel<32><<<dim3((n + TB - 1) / TB, 4), TB>>>(Mp, srcs, dsts, Ap, E);

        int nc = NDRUG * (DEMB / 4);
        combine_kernel<32, false><<<(nc + TB - 1) / TB, TB>>>(
            Ap.p[0], deg + 0 * NDRUG, Ap.p[2], deg + 2 * NDRUG, b2d, out, NDRUG);
        combine_kernel<32, false><<<(nc + TB - 1) / TB, TB>>>(
            Ap.p[1], deg + 1 * NDRUG, Ap.p[3], deg + 3 * NDRUG, b2g,
            out + (size_t)NDRUG * DEMB, NGENE);
    }
}

// round 4
// speedup vs baseline: 3.1201x; 3.1201x over previous
#include <cuda_runtime.h>

constexpr int NDRUG = 50000;
constexpr int NGENE = 50000;
constexpr int DHID  = 64;
constexpr int DEMB  = 32;
constexpr int EMAX  = 600000;

// Scratch (device globals — no allocation allowed)
__device__ float g_tm[4][NDRUG * DHID];        // transformed src features per relation
__device__ float g_h[2][NDRUG * DHID];         // hidden layer outputs (hd, hg)
__device__ int   g_deg[4 * NDRUG];             // per-relation in-degree (int)
__device__ int   g_rowstart[4 * (NDRUG + 1)];  // CSR row offsets per relation
__device__ int   g_cursor[4 * (NDRUG + 1)];    // fill cursors (copy of rowstart)
__device__ int   g_csr[4 * EMAX];              // CSR src indices per relation

struct Ptr4  { const float* p[4]; };
struct Iptr4 { const int*   p[4]; };
struct Fptr4 { float*       p[4]; };

// ---------------------------------------------------------------------------
// int degree histogram, all 4 relations (gridDim.y = relation)
// ---------------------------------------------------------------------------
__global__ void degree4_kernel(Iptr4 dst, int* __restrict__ deg, int E) {
    int r = blockIdx.y;
    int i = blockIdx.x * blockDim.x + threadIdx.x;
    if (i < E) atomicAdd(&deg[r * NDRUG + dst.p[r][i]], 1);
}

// ---------------------------------------------------------------------------
// exclusive prefix scan of degrees -> rowstart; 1 block (1024 thr) per relation
// ---------------------------------------------------------------------------
__global__ __launch_bounds__(1024)
void scan4_kernel(const int* __restrict__ deg, int* __restrict__ rowstart) {
    int r = blockIdx.x;
    const int* dg = deg + r * NDRUG;
    int* rs = rowstart + (size_t)r * (NDRUG + 1);
    __shared__ int warpsum[32];
    __shared__ int carry_sh;
    int t = threadIdx.x, lane = t & 31, w = t >> 5;
    if (t == 0) carry_sh = 0;
    __syncthreads();
    for (int base = 0; base < NDRUG; base += 1024) {
        int idx = base + t;
        int v = (idx < NDRUG) ? dg[idx] : 0;
        int x = v;
#pragma unroll
        for (int off = 1; off < 32; off <<= 1) {
            int y = __shfl_up_sync(~0u, x, off);
            if (lane >= off) x += y;
        }
        if (lane == 31) warpsum[w] = x;
        __syncthreads();
        if (w == 0) {
            int s = warpsum[lane];
#pragma unroll
            for (int off = 1; off < 32; off <<= 1) {
                int y = __shfl_up_sync(~0u, s, off);
                if (lane >= off) s += y;
            }
            warpsum[lane] = s;
        }
        __syncthreads();
        int woff = (w > 0) ? warpsum[w - 1] : 0;
        int incl = x + woff;
        int carry = carry_sh;
        if (idx < NDRUG) rs[idx] = carry + incl - v;
        __syncthreads();
        if (t == 1023) carry_sh = carry + incl;
        __syncthreads();
    }
    if (t == 0) rs[NDRUG] = carry_sh;
}

// ---------------------------------------------------------------------------
// CSR fill: csr[rowstart[dst]++] = src  (int atomics on cursors)
// ---------------------------------------------------------------------------
__global__ void fill4_kernel(Iptr4 src, Iptr4 dst, int* __restrict__ cursor,
                             int* __restrict__ csr, int E) {
    int r = blockIdx.y;
    int i = blockIdx.x * blockDim.x + threadIdx.x;
    if (i >= E) return;
    int d = dst.p[r][i];
    int pos = atomicAdd(&cursor[(size_t)r * (NDRUG + 1) + d], 1);
    csr[(size_t)r * EMAX + pos] = src.p[r][i];
}

// ---------------------------------------------------------------------------
// Tiled fp32 GEMM, 4 relations per launch: Y[r][M,N] = X[r][M,K] @ W[r][K,N]
// ---------------------------------------------------------------------------
template<int K, int N>
__launch_bounds__(256)
__global__ void gemm4_kernel(Ptr4 Xa, Ptr4 Wa, Fptr4 Ya, int M) {
    constexpr int BM = 128, BK = 32;
    constexpr int TM = 8, TN = N / 16;
    const int r = blockIdx.y;
    const float* __restrict__ X = Xa.p[r];
    const float* __restrict__ W = Wa.p[r];
    float* __restrict__ Y = Ya.p[r];

    __shared__ float Xs[BM][BK + 4];
    __shared__ float Ws[BK][N + 4];
    const int tid  = threadIdx.x;
    const int trow = tid >> 4;
    const int tcol = tid & 15;
    const int m0   = blockIdx.x * BM;

    float acc[TM][TN];
#pragma unroll
    for (int i = 0; i < TM; i++)
#pragma unroll
        for (int j = 0; j < TN; j++) acc[i][j] = 0.f;

    for (int k0 = 0; k0 < K; k0 += BK) {
#pragma unroll
        for (int i = 0; i < 4; i++) {
            int lin = tid + i * 256;
            int row = lin >> 3;
            int c4  = (lin & 7) * 4;
            int gr  = m0 + row;
            float4 v = make_float4(0.f, 0.f, 0.f, 0.f);
            if (gr < M) v = *(const float4*)(X + (size_t)gr * K + k0 + c4);
            Xs[row][c4 + 0] = v.x; Xs[row][c4 + 1] = v.y;
            Xs[row][c4 + 2] = v.z; Xs[row][c4 + 3] = v.w;
        }
        constexpr int WF4 = BK * N / 4;
#pragma unroll
        for (int i = 0; i < (WF4 + 255) / 256; i++) {
            int lin = tid + i * 256;
            if (lin < WF4) {
                int row = lin / (N / 4);
                int c4  = (lin % (N / 4)) * 4;
                float4 v = *(const float4*)(W + (size_t)(k0 + row) * N + c4);
                Ws[row][c4 + 0] = v.x; Ws[row][c4 + 1] = v.y;
                Ws[row][c4 + 2] = v.z; Ws[row][c4 + 3] = v.w;
            }
        }
        __syncthreads();
#pragma unroll
        for (int k = 0; k < BK; k++) {
            float a[TM], b[TN];
#pragma unroll
            for (int i = 0; i < TM; i++) a[i] = Xs[trow * TM + i][k];
#pragma unroll
            for (int j = 0; j < TN; j++) b[j] = Ws[k][tcol * TN + j];
#pragma unroll
            for (int i = 0; i < TM; i++)
#pragma unroll
                for (int j = 0; j < TN; j++) acc[i][j] += a[i] * b[j];
        }
        __syncthreads();
    }
#pragma unroll
    for (int i = 0; i < TM; i++) {
        int gr = m0 + trow * TM + i;
        if (gr < M) {
#pragma unroll
            for (int j = 0; j < TN; j++)
                Y[(size_t)gr * N + tcol * TN + j] = acc[i][j];
        }
    }
}

// ---------------------------------------------------------------------------
// Fused gather: one warp per dst node; mean over relation A + mean over
// relation B + bias (+relu). D=64 -> float2/lane, D=32 -> float/lane.
// ---------------------------------------------------------------------------
template<int D, bool RELU>
__launch_bounds__(256)
__global__ void gather2_kernel(const float* __restrict__ tmA, const int* __restrict__ csrA,
                               const int* __restrict__ rsA,
                               const float* __restrict__ tmB, const int* __restrict__ csrB,
                               const int* __restrict__ rsB,
                               const float* __restrict__ bias, float* __restrict__ out, int n) {
    constexpr int V = D / 32;            // floats per lane
    int warp = (blockIdx.x * blockDim.x + threadIdx.x) >> 5;
    int lane = threadIdx.x & 31;
    if (warp >= n) return;

    float res[V];
#pragma unroll
    for (int j = 0; j < V; j++) res[j] = bias[lane * V + j];

    // ---- relation A ----
    {
        int s = rsA[warp], e = rsA[warp + 1];
        float inv = 1.0f / (float)max(e - s, 1);
        float acc[V];
#pragma unroll
        for (int j = 0; j < V; j++) acc[j] = 0.f;
        int i = s;
        for (; i + 1 < e; i += 2) {
            int s0 = csrA[i], s1 = csrA[i + 1];
            if (V == 2) {
                float2 v0 = ((const float2*)(tmA + (size_t)s0 * D))[lane];
                float2 v1 = ((const float2*)(tmA + (size_t)s1 * D))[lane];
                acc[0] += v0.x + v1.x;
                acc[1] += v0.y + v1.y;
            } else {
                acc[0] += tmA[(size_t)s0 * D + lane] + tmA[(size_t)s1 * D + lane];
            }
        }
        if (i < e) {
            int s0 = csrA[i];
            if (V == 2) {
                float2 v0 = ((const float2*)(tmA + (size_t)s0 * D))[lane];
                acc[0] += v0.x; acc[1] += v0.y;
            } else {
                acc[0] += tmA[(size_t)s0 * D + lane];
            }
        }
#pragma unroll
        for (int j = 0; j < V; j++) res[j] += acc[j] * inv;
    }
    // ---- relation B ----
    {
        int s = rsB[warp], e = rsB[warp + 1];
        float inv = 1.0f / (float)max(e - s, 1);
        float acc[V];
#pragma unroll
        for (int j = 0; j < V; j++) acc[j] = 0.f;
        int i = s;
        for (; i + 1 < e; i += 2) {
            int s0 = csrB[i], s1 = csrB[i + 1];
            if (V == 2) {
                float2 v0 = ((const float2*)(tmB + (size_t)s0 * D))[lane];
                float2 v1 = ((const float2*)(tmB + (size_t)s1 * D))[lane];
                acc[0] += v0.x + v1.x;
                acc[1] += v0.y + v1.y;
            } else {
                acc[0] += tmB[(size_t)s0 * D + lane] + tmB[(size_t)s1 * D + lane];
            }
        }
        if (i < e) {
            int s0 = csrB[i];
            if (V == 2) {
                float2 v0 = ((const float2*)(tmB + (size_t)s0 * D))[lane];
                acc[0] += v0.x; acc[1] += v0.y;
            } else {
                acc[0] += tmB[(size_t)s0 * D + lane];
            }
        }
#pragma unroll
        for (int j = 0; j < V; j++) res[j] += acc[j] * inv;
    }

    if (RELU) {
#pragma unroll
        for (int j = 0; j < V; j++) res[j] = fmaxf(res[j], 0.f);
    }
    if (V == 2) {
        float2 o; o.x = res[0]; o.y = res[1];
        ((float2*)(out + (size_t)warp * D))[lane] = o;
    } else {
        out[(size_t)warp * D + lane] = res[0];
    }
}

// ---------------------------------------------------------------------------
// Orchestration
// Relations: 0=dd (drug->drug), 1=dg (drug->gene), 2=gd (gene->drug), 3=gg
//   hd = mean_dd + mean_gd + b_drug ; hg = mean_dg + mean_gg + b_gene
// ---------------------------------------------------------------------------
extern "C" void kernel_launch(void* const* d_in, const int* in_sizes, int n_in,
                              void* d_out, int out_size) {
    const float* xd = (const float*)d_in[0];
    const float* xg = (const float*)d_in[1];
    const int* es[8];
    for (int i = 0; i < 8; i++) es[i] = (const int*)d_in[2 + i];
    const float* W1[4] = {(const float*)d_in[10], (const float*)d_in[11],
                          (const float*)d_in[12], (const float*)d_in[13]};
    const float* b1d = (const float*)d_in[14];
    const float* b1g = (const float*)d_in[15];
    const float* W2[4] = {(const float*)d_in[16], (const float*)d_in[17],
                          (const float*)d_in[18], (const float*)d_in[19]};
    const float* b2d = (const float*)d_in[20];
    const float* b2g = (const float*)d_in[21];
    float* out = (float*)d_out;
    const int E = in_sizes[2];

    float *tm, *h;
    int *deg, *rowstart, *cursor, *csr;
    cudaGetSymbolAddress((void**)&tm,       g_tm);
    cudaGetSymbolAddress((void**)&h,        g_h);
    cudaGetSymbolAddress((void**)&deg,      g_deg);
    cudaGetSymbolAddress((void**)&rowstart, g_rowstart);
    cudaGetSymbolAddress((void**)&cursor,   g_cursor);
    cudaGetSymbolAddress((void**)&csr,      g_csr);

    const int TB = 256;
    const int gblk = (NDRUG + 127) / 128;

    Iptr4 srcs = {{es[0], es[2], es[4], es[6]}};
    Iptr4 dsts = {{es[1], es[3], es[5], es[7]}};

    // --- CSR build (shared by both layers) ---
    cudaMemsetAsync(deg, 0, sizeof(int) * 4 * NDRUG, 0);
    degree4_kernel<<<dim3((E + TB - 1) / TB, 4), TB>>>(dsts, deg, E);
    scan4_kernel<<<4, 1024>>>(deg, rowstart);
    cudaMemcpyAsync(cursor, rowstart, sizeof(int) * 4 * (NDRUG + 1),
                    cudaMemcpyDeviceToDevice, 0);
    fill4_kernel<<<dim3((E + TB - 1) / TB, 4), TB>>>(srcs, dsts, cursor, csr, E);

    const int* rs[4]  = {rowstart, rowstart + (NDRUG + 1), rowstart + 2 * (NDRUG + 1),
                         rowstart + 3 * (NDRUG + 1)};
    const int* cs[4]  = {csr, csr + EMAX, csr + 2 * (size_t)EMAX, csr + 3 * (size_t)EMAX};

    // --- layer 1: 128 -> 64, relu ---
    {
        Ptr4  X1 = {{xd, xd, xg, xg}};
        Ptr4  Wp = {{W1[0], W1[1], W1[2], W1[3]}};
        Fptr4 Yp = {{tm + 0 * (size_t)NDRUG * DHID, tm + 1 * (size_t)NDRUG * DHID,
                     tm + 2 * (size_t)NDRUG * DHID, tm + 3 * (size_t)NDRUG * DHID}};
        gemm4_kernel<128, 64><<<dim3(gblk, 4), 256>>>(X1, Wp, Yp, NDRUG);

        int blocks = (NDRUG * 32 + TB - 1) / TB;   // warp per node
        gather2_kernel<64, true><<<blocks, TB>>>(
            Yp.p[0], cs[0], rs[0], Yp.p[2], cs[2], rs[2], b1d, h, NDRUG);
        gather2_kernel<64, true><<<blocks, TB>>>(
            Yp.p[1], cs[1], rs[1], Yp.p[3], cs[3], rs[3], b1g,
            h + (size_t)NDRUG * DHID, NGENE);
    }

    // --- layer 2: 64 -> 32, no relu ---
    {
        const float* hd = h;
        const float* hg = h + (size_t)NDRUG * DHID;
        Ptr4  X2 = {{hd, hd, hg, hg}};
        Ptr4  Wp = {{W2[0], W2[1], W2[2], W2[3]}};
        Fptr4 Yp = {{tm + 0 * (size_t)NDRUG * DEMB, tm + 1 * (size_t)NDRUG * DEMB,
                     tm + 2 * (size_t)NDRUG * DEMB, tm + 3 * (size_t)NDRUG * DEMB}};
        gemm4_kernel<64, 32><<<dim3(gblk, 4), 256>>>(X2, Wp, Yp, NDRUG);

        int blocks = (NDRUG * 32 + TB - 1) / TB;
        gather2_kernel<32, false><<<blocks, TB>>>(
            Yp.p[0], cs[0], rs[0], Yp.p[2], cs[2], rs[2], b2d, out, NDRUG);
        gather2_kernel<32, false><<<blocks, TB>>>(
            Yp.p[1], cs[1], rs[1], Yp.p[3], cs[3], rs[3], b2g,
            out + (size_t)NDRUG * DEMB, NGENE);
    }
}

// round 5
// speedup vs baseline: 3.4071x; 1.0920x over previous
#include <cuda_runtime.h>

constexpr int NDRUG = 50000;
constexpr int NGENE = 50000;
constexpr int DHID  = 64;
constexpr int DEMB  = 32;
constexpr int EMAX  = 600000;

// Scratch (device globals — no allocation allowed)
__device__ float g_tm[2][NDRUG * 128];         // packed transformed features (per src type)
__device__ float g_h[2][NDRUG * DHID];         // hidden outputs (hd, hg)
__device__ float g_wp1[2][128 * 128];          // packed layer-1 weights
__device__ float g_wp2[2][64 * 64];            // packed layer-2 weights
__device__ int   g_deg[4 * NDRUG];
__device__ int   g_rowstart[4 * (NDRUG + 1)];
__device__ int   g_cursor[4 * (NDRUG + 1)];
__device__ int   g_csr[4 * EMAX];

struct Iptr4 { const int* p[4]; };
struct Ptr2  { const float* p[2]; };
struct Fptr2 { float* p[2]; };

// ---------------------------------------------------------------------------
// int degree histogram, 4 relations
// ---------------------------------------------------------------------------
__global__ void degree4_kernel(Iptr4 dst, int* __restrict__ deg, int E) {
    int r = blockIdx.y;
    int i = blockIdx.x * blockDim.x + threadIdx.x;
    if (i < E) atomicAdd(&deg[r * NDRUG + dst.p[r][i]], 1);
}

// ---------------------------------------------------------------------------
// exclusive prefix scan of degrees -> rowstart; 1 block per relation
// ---------------------------------------------------------------------------
__global__ __launch_bounds__(1024)
void scan4_kernel(const int* __restrict__ deg, int* __restrict__ rowstart) {
    int r = blockIdx.x;
    const int* dg = deg + r * NDRUG;
    int* rs = rowstart + (size_t)r * (NDRUG + 1);
    __shared__ int warpsum[32];
    __shared__ int carry_sh;
    int t = threadIdx.x, lane = t & 31, w = t >> 5;
    if (t == 0) carry_sh = 0;
    __syncthreads();
    for (int base = 0; base < NDRUG; base += 1024) {
        int idx = base + t;
        int v = (idx < NDRUG) ? dg[idx] : 0;
        int x = v;
#pragma unroll
        for (int off = 1; off < 32; off <<= 1) {
            int y = __shfl_up_sync(~0u, x, off);
            if (lane >= off) x += y;
        }
        if (lane == 31) warpsum[w] = x;
        __syncthreads();
        if (w == 0) {
            int s = warpsum[lane];
#pragma unroll
            for (int off = 1; off < 32; off <<= 1) {
                int y = __shfl_up_sync(~0u, s, off);
                if (lane >= off) s += y;
            }
            warpsum[lane] = s;
        }
        __syncthreads();
        int woff = (w > 0) ? warpsum[w - 1] : 0;
        int incl = x + woff;
        int carry = carry_sh;
        if (idx < NDRUG) rs[idx] = carry + incl - v;
        __syncthreads();
        if (t == 1023) carry_sh = carry + incl;
        __syncthreads();
    }
    if (t == 0) rs[NDRUG] = carry_sh;
}

// ---------------------------------------------------------------------------
// CSR fill
// ---------------------------------------------------------------------------
__global__ void fill4_kernel(Iptr4 src, Iptr4 dst, int* __restrict__ cursor,
                             int* __restrict__ csr, int E) {
    int r = blockIdx.y;
    int i = blockIdx.x * blockDim.x + threadIdx.x;
    if (i >= E) return;
    int d = dst.p[r][i];
    int pos = atomicAdd(&cursor[(size_t)r * (NDRUG + 1) + d], 1);
    csr[(size_t)r * EMAX + pos] = src.p[r][i];
}

// ---------------------------------------------------------------------------
// Pack two [K,N] weight matrices into one [K,2N]
// ---------------------------------------------------------------------------
struct PackArgs { const float* a; const float* b; float* o; int K; int N; };
__global__ void pack4_kernel(PackArgs p0, PackArgs p1, PackArgs p2, PackArgs p3) {
    PackArgs p = (blockIdx.y == 0) ? p0 : (blockIdx.y == 1) ? p1
               : (blockIdx.y == 2) ? p2 : p3;
    int idx = blockIdx.x * blockDim.x + threadIdx.x;
    int tot = p.K * 2 * p.N;
    if (idx >= tot) return;
    int c = idx % (2 * p.N);
    int k = idx / (2 * p.N);
    p.o[idx] = (c < p.N) ? p.a[k * p.N + c] : p.b[k * p.N + c - p.N];
}

// ---------------------------------------------------------------------------
// Tiled fp32 GEMM with 8x8 thread tile + vectorized smem fragment loads.
// Y[y][M,N] = X[y][M,K] @ W[y][K,N], gridDim.y = 2 (one per src type).
// Xs stored transposed [BK][BM] so A-fragments load as LDS.128.
// ---------------------------------------------------------------------------
template<int K, int N>
__launch_bounds__((N / 8) * 16, 2)
__global__ void gemmp_kernel(Ptr2 Xa, Ptr2 Wa, Fptr2 Ya, int M) {
    constexpr int BM = 128, BK = 16, TM = 8, TN = 8;
    constexpr int TCOLS = N / TN;               // 16 (N=128) or 8 (N=64)
    constexpr int THREADS = (BM / TM) * TCOLS;  // 256 or 128
    const int y = blockIdx.y;
    const float* __restrict__ X = Xa.p[y];
    const float* __restrict__ W = Wa.p[y];
    float* __restrict__ Y = Ya.p[y];

    __shared__ float Xs[BK][BM + 4];   // stride 132 floats (16B-aligned rows)
    __shared__ float Ws[BK][N + 4];

    const int tid  = threadIdx.x;
    const int trow = tid / TCOLS;       // 0..15
    const int tcol = tid % TCOLS;
    const int m0   = blockIdx.x * BM;

    float acc[TM][TN];
#pragma unroll
    for (int i = 0; i < TM; i++)
#pragma unroll
        for (int j = 0; j < TN; j++) acc[i][j] = 0.f;

    for (int k0 = 0; k0 < K; k0 += BK) {
        // load X tile [BM x BK] transposed into Xs[BK][BM]
        constexpr int XF4 = BM * BK / 4;       // 512 float4
#pragma unroll
        for (int it = 0; it < XF4 / THREADS; it++) {
            int lin = tid + it * THREADS;
            int row = lin >> 2;                // 4 float4 per row
            int kk  = (lin & 3) * 4;
            int gr  = m0 + row;
            float4 v = make_float4(0.f, 0.f, 0.f, 0.f);
            if (gr < M) v = *(const float4*)(X + (size_t)gr * K + k0 + kk);
            Xs[kk + 0][row] = v.x; Xs[kk + 1][row] = v.y;
            Xs[kk + 2][row] = v.z; Xs[kk + 3][row] = v.w;
        }
        // load W tile [BK x N]
        constexpr int WF4 = BK * N / 4;
#pragma unroll
        for (int it = 0; it < WF4 / THREADS; it++) {
            int lin = tid + it * THREADS;
            int row = lin / (N / 4);
            int c4  = (lin % (N / 4)) * 4;
            float4 v = *(const float4*)(W + (size_t)(k0 + row) * N + c4);
            Ws[row][c4 + 0] = v.x; Ws[row][c4 + 1] = v.y;
            Ws[row][c4 + 2] = v.z; Ws[row][c4 + 3] = v.w;
        }
        __syncthreads();
#pragma unroll
        for (int k = 0; k < BK; k++) {
            float4 a0 = *(const float4*)&Xs[k][trow * TM];
            float4 a1 = *(const float4*)&Xs[k][trow * TM + 4];
            float4 b0 = *(const float4*)&Ws[k][tcol * TN];
            float4 b1 = *(const float4*)&Ws[k][tcol * TN + 4];
            float a[TM] = {a0.x, a0.y, a0.z, a0.w, a1.x, a1.y, a1.z, a1.w};
            float b[TN] = {b0.x, b0.y, b0.z, b0.w, b1.x, b1.y, b1.z, b1.w};
#pragma unroll
            for (int i = 0; i < TM; i++)
#pragma unroll
                for (int j = 0; j < TN; j++) acc[i][j] += a[i] * b[j];
        }
        __syncthreads();
    }
#pragma unroll
    for (int i = 0; i < TM; i++) {
        int gr = m0 + trow * TM + i;
        if (gr < M) {
            *(float4*)(Y + (size_t)gr * N + tcol * TN)     =
                make_float4(acc[i][0], acc[i][1], acc[i][2], acc[i][3]);
            *(float4*)(Y + (size_t)gr * N + tcol * TN + 4) =
                make_float4(acc[i][4], acc[i][5], acc[i][6], acc[i][7]);
        }
    }
}

// ---------------------------------------------------------------------------
// Fused dual gather: gridDim.y selects (drug | gene) config.
// One warp per dst node: mean over rel A + mean over rel B + bias (+relu).
// tm rows have leading dim LD (packed layout).
// ---------------------------------------------------------------------------
struct GatherCfg {
    const float* tmA; const int* csrA; const int* rsA;
    const float* tmB; const int* csrB; const int* rsB;
    const float* bias; float* out;
};

template<int D, int LD, bool RELU>
__launch_bounds__(256)
__global__ void gather_dual_kernel(GatherCfg c0, GatherCfg c1, int n) {
    constexpr int V = D / 32;           // floats per lane
    const GatherCfg c = blockIdx.y ? c1 : c0;
    int warp = (blockIdx.x * blockDim.x + threadIdx.x) >> 5;
    int lane = threadIdx.x & 31;
    if (warp >= n) return;

    float res[V];
#pragma unroll
    for (int j = 0; j < V; j++) res[j] = c.bias[lane * V + j];

#pragma unroll
    for (int rel = 0; rel < 2; rel++) {
        const float* tm  = rel ? c.tmB  : c.tmA;
        const int*   csr = rel ? c.csrB : c.csrA;
        const int*   rs  = rel ? c.rsB  : c.rsA;
        int s = rs[warp], e = rs[warp + 1];
        float inv = 1.0f / (float)max(e - s, 1);
        float acc[V];
#pragma unroll
        for (int j = 0; j < V; j++) acc[j] = 0.f;
        int i = s;
        for (; i + 4 <= e; i += 4) {
            int s0 = csr[i], s1 = csr[i + 1], s2 = csr[i + 2], s3 = csr[i + 3];
            if (V == 2) {
                float2 v0 = ((const float2*)(tm + (size_t)s0 * LD))[lane];
                float2 v1 = ((const float2*)(tm + (size_t)s1 * LD))[lane];
                float2 v2 = ((const float2*)(tm + (size_t)s2 * LD))[lane];
                float2 v3 = ((const float2*)(tm + (size_t)s3 * LD))[lane];
                acc[0] += (v0.x + v1.x) + (v2.x + v3.x);
                acc[1] += (v0.y + v1.y) + (v2.y + v3.y);
            } else {
                float v0 = tm[(size_t)s0 * LD + lane];
                float v1 = tm[(size_t)s1 * LD + lane];
                float v2 = tm[(size_t)s2 * LD + lane];
                float v3 = tm[(size_t)s3 * LD + lane];
                acc[0] += (v0 + v1) + (v2 + v3);
            }
        }
        for (; i < e; i++) {
            int s0 = csr[i];
            if (V == 2) {
                float2 v0 = ((const float2*)(tm + (size_t)s0 * LD))[lane];
                acc[0] += v0.x; acc[1] += v0.y;
            } else {
                acc[0] += tm[(size_t)s0 * LD + lane];
            }
        }
#pragma unroll
        for (int j = 0; j < V; j++) res[j] += acc[j] * inv;
    }

    if (RELU) {
#pragma unroll
        for (int j = 0; j < V; j++) res[j] = fmaxf(res[j], 0.f);
    }
    if (V == 2) {
        ((float2*)(c.out + (size_t)warp * D))[lane] = make_float2(res[0], res[1]);
    } else {
        c.out[(size_t)warp * D + lane] = res[0];
    }
}

// ---------------------------------------------------------------------------
// Orchestration
// Relations: 0=dd, 1=dg, 2=gd, 3=gg.
// Packed GEMMs: Y_d = x_d @ [W_dd | W_dg], Y_g = x_g @ [W_gd | W_gg].
// ---------------------------------------------------------------------------
extern "C" void kernel_launch(void* const* d_in, const int* in_sizes, int n_in,
                              void* d_out, int out_size) {
    const float* xd = (const float*)d_in[0];
    const float* xg = (const float*)d_in[1];
    const int* es[8];
    for (int i = 0; i < 8; i++) es[i] = (const int*)d_in[2 + i];
    const float* W1[4] = {(const float*)d_in[10], (const float*)d_in[11],
                          (const float*)d_in[12], (const float*)d_in[13]};
    const float* b1d = (const float*)d_in[14];
    const float* b1g = (const float*)d_in[15];
    const float* W2[4] = {(const float*)d_in[16], (const float*)d_in[17],
                          (const float*)d_in[18], (const float*)d_in[19]};
    const float* b2d = (const float*)d_in[20];
    const float* b2g = (const float*)d_in[21];
    float* out = (float*)d_out;
    const int E = in_sizes[2];

    float *tm, *h, *wp1, *wp2;
    int *deg, *rowstart, *cursor, *csr;
    cudaGetSymbolAddress((void**)&tm,       g_tm);
    cudaGetSymbolAddress((void**)&h,        g_h);
    cudaGetSymbolAddress((void**)&wp1,      g_wp1);
    cudaGetSymbolAddress((void**)&wp2,      g_wp2);
    cudaGetSymbolAddress((void**)&deg,      g_deg);
    cudaGetSymbolAddress((void**)&rowstart, g_rowstart);
    cudaGetSymbolAddress((void**)&cursor,   g_cursor);
    cudaGetSymbolAddress((void**)&csr,      g_csr);

    const int TB = 256;
    const int gblk = (NDRUG + 127) / 128;

    Iptr4 srcs = {{es[0], es[2], es[4], es[6]}};
    Iptr4 dsts = {{es[1], es[3], es[5], es[7]}};

    float* tm0 = tm;
    float* tm1 = tm + (size_t)NDRUG * 128;
    float* wp1d = wp1;                 float* wp1g = wp1 + 128 * 128;
    float* wp2d = wp2;                 float* wp2g = wp2 + 64 * 64;

    // --- weight packing (independent of everything else) ---
    {
        PackArgs p0 = {W1[0], W1[1], wp1d, 128, 64};   // [W1_dd | W1_dg]
        PackArgs p1 = {W1[2], W1[3], wp1g, 128, 64};   // [W1_gd | W1_gg]
        PackArgs p2 = {W2[0], W2[1], wp2d, 64, 32};    // [W2_dd | W2_dg]
        PackArgs p3 = {W2[2], W2[3], wp2g, 64, 32};    // [W2_gd | W2_gg]
        pack4_kernel<<<dim3(64, 4), 256>>>(p0, p1, p2, p3);
    }

    // --- CSR build (shared by both layers) ---
    cudaMemsetAsync(deg, 0, sizeof(int) * 4 * NDRUG, 0);
    degree4_kernel<<<dim3((E + TB - 1) / TB, 4), TB>>>(dsts, deg, E);
    scan4_kernel<<<4, 1024>>>(deg, rowstart);
    cudaMemcpyAsync(cursor, rowstart, sizeof(int) * 4 * (NDRUG + 1),
                    cudaMemcpyDeviceToDevice, 0);
    fill4_kernel<<<dim3((E + TB - 1) / TB, 4), TB>>>(srcs, dsts, cursor, csr, E);

    const int* rs[4] = {rowstart, rowstart + (NDRUG + 1),
                        rowstart + 2 * (NDRUG + 1), rowstart + 3 * (NDRUG + 1)};
    const int* cs[4] = {csr, csr + EMAX, csr + 2 * (size_t)EMAX, csr + 3 * (size_t)EMAX};

    int gather_blocks = (NDRUG * 32 + TB - 1) / TB;

    // --- layer 1: packed GEMM (K=128, N=128), then fused gather ---
    {
        Ptr2  X = {{xd, xg}};
        Ptr2  W = {{wp1d, wp1g}};
        Fptr2 Y = {{tm0, tm1}};
        gemmp_kernel<128, 128><<<dim3(gblk, 2), 256>>>(X, W, Y, NDRUG);

        GatherCfg cd = {tm0,      cs[0], rs[0], tm1,      cs[2], rs[2], b1d, h};
        GatherCfg cg = {tm0 + 64, cs[1], rs[1], tm1 + 64, cs[3], rs[3], b1g,
                        h + (size_t)NDRUG * DHID};
        gather_dual_kernel<64, 128, true><<<dim3(gather_blocks, 2), TB>>>(cd, cg, NDRUG);
    }

    // --- layer 2: packed GEMM (K=64, N=64), then fused gather ---
    {
        const float* hd = h;
        const float* hg = h + (size_t)NDRUG * DHID;
        Ptr2  X = {{hd, hg}};
        Ptr2  W = {{wp2d, wp2g}};
        Fptr2 Y = {{tm0, tm1}};
        gemmp_kernel<64, 64><<<dim3(gblk, 2), 128>>>(X, W, Y, NDRUG);

        GatherCfg cd = {tm0,      cs[0], rs[0], tm1,      cs[2], rs[2], b2d, out};
        GatherCfg cg = {tm0 + 32, cs[1], rs[1], tm1 + 32, cs[3], rs[3], b2g,
                        out + (size_t)NDRUG * DEMB};
        gather_dual_kernel<32, 64, false><<<dim3(gather_blocks, 2), TB>>>(cd, cg, NDRUG);
    }
}